// round 1
// baseline (speedup 1.0000x reference)
#include <cuda_runtime.h>
#include <math.h>

// Problem constants
#define Nn   16384
#define Ee   65536
#define Gg   64
#define INF  63
#define HID  2048
#define MIDD 1024
#define NCLS 18
#define SLOPE 0.01f
#define EPS   1e-5f

// ---------------- scratch (device globals; no allocation allowed) ----------------
__device__ float g_nm[(size_t)Nn * HID];   // neighbor mean buffer
__device__ float g_x [(size_t)Nn * HID];   // current activations
__device__ float g_y [(size_t)Nn * HID];   // GEMM output
__device__ float g_deg[Nn];
__device__ float g_scale[HID];
__device__ float g_shift[HID];
__device__ float g_hg[Gg * HID];
__device__ float g_cnt[Gg];
__device__ float g_t1[Gg * HID];
__device__ float g_t2[Gg * MIDD];

// ---------------- degree ----------------
__global__ void deg_kernel(const int* __restrict__ dst, float* __restrict__ deg) {
    int i = blockIdx.x * blockDim.x + threadIdx.x;
    if (i < Ee) atomicAdd(&deg[dst[i]], 1.0f);
}

// ---------------- edge scatter-add: out[dst[e], :] += x[src[e], :] ----------------
// grid: (E, ceil(F/blockDim)), block: blockDim threads
__global__ void scatter_add(const float* __restrict__ x, const int* __restrict__ src,
                            const int* __restrict__ dst, float* __restrict__ out, int F) {
    int e = blockIdx.x;
    int f = blockIdx.y * blockDim.x + threadIdx.x;
    if (f >= F) return;
    int s = src[e], d = dst[e];
    atomicAdd(&out[(size_t)d * F + f], x[(size_t)s * F + f]);
}

// ---------------- divide rows by max(deg,1) ----------------
// grid: (ceil(F/blockDim), N)
__global__ void row_div(float* __restrict__ nm, const float* __restrict__ deg, int F) {
    int row = blockIdx.y;
    int f = blockIdx.x * blockDim.x + threadIdx.x;
    if (f >= F) return;
    float d = deg[row];
    nm[(size_t)row * F + f] *= 1.0f / fmaxf(d, 1.0f);
}

// ---------------- dual-source SGEMM: C = A1@W1 + A2@W2 + bias ----------------
// A row-major MxK, W row-major KxNc, C MxNc. A2/W2 optional (nullptr).
#define BM 128
#define BN 128
#define BK 16
#define TM 8
#define TN 8

__global__ __launch_bounds__(256, 2)
void sgemm_dual(const float* __restrict__ A1, const float* __restrict__ W1,
                const float* __restrict__ A2, const float* __restrict__ W2,
                const float* __restrict__ bias, float* __restrict__ C,
                int M, int Nc, int K, int do_lrelu) {
    __shared__ float As[BK][BM + 4];
    __shared__ float Bs[BK][BN];
    int tid = threadIdx.x;
    int block_row = blockIdx.y * BM;
    int block_col = blockIdx.x * BN;
    int tr = tid / (BN / TN);   // 0..15
    int tc = tid % (BN / TN);   // 0..15

    float acc[TM][TN];
    #pragma unroll
    for (int i = 0; i < TM; i++)
        #pragma unroll
        for (int j = 0; j < TN; j++) acc[i][j] = 0.0f;

    int nsrc = (A2 != nullptr) ? 2 : 1;
    for (int s = 0; s < nsrc; s++) {
        const float* A = s ? A2 : A1;
        const float* W = s ? W2 : W1;
        for (int k0 = 0; k0 < K; k0 += BK) {
            // load A tile (BM x BK), transposed into As[k][m]
            #pragma unroll
            for (int i = tid; i < BM * BK; i += 256) {
                int m = i / BK, k = i % BK;
                int gr = block_row + m, gk = k0 + k;
                As[k][m] = (gr < M && gk < K) ? A[(size_t)gr * K + gk] : 0.0f;
            }
            // load W tile (BK x BN)
            #pragma unroll
            for (int i = tid; i < BK * BN; i += 256) {
                int k = i / BN, n = i % BN;
                int gk = k0 + k, gc = block_col + n;
                Bs[k][n] = (gk < K && gc < Nc) ? W[(size_t)gk * Nc + gc] : 0.0f;
            }
            __syncthreads();
            #pragma unroll
            for (int k = 0; k < BK; k++) {
                float ra[TM], rb[TN];
                #pragma unroll
                for (int i = 0; i < TM; i++) ra[i] = As[k][tr * TM + i];
                #pragma unroll
                for (int j = 0; j < TN; j++) rb[j] = Bs[k][tc * TN + j];
                #pragma unroll
                for (int i = 0; i < TM; i++)
                    #pragma unroll
                    for (int j = 0; j < TN; j++)
                        acc[i][j] += ra[i] * rb[j];
            }
            __syncthreads();
        }
    }
    // epilogue
    #pragma unroll
    for (int i = 0; i < TM; i++) {
        int gr = block_row + tr * TM + i;
        if (gr >= M) continue;
        #pragma unroll
        for (int j = 0; j < TN; j++) {
            int gc = block_col + tc * TN + j;
            if (gc >= Nc) continue;
            float v = acc[i][j] + (bias ? bias[gc] : 0.0f);
            if (do_lrelu) v = (v > 0.0f) ? v : SLOPE * v;
            C[(size_t)gr * Nc + gc] = v;
        }
    }
}

// ---------------- BN stats: per-column mean/var -> scale/shift ----------------
// grid: C/32 blocks of 256 threads (32 cols x 8 row-groups)
__global__ void bn_stats(const float* __restrict__ X,
                         const float* __restrict__ gamma, const float* __restrict__ beta,
                         float* __restrict__ scale, float* __restrict__ shift,
                         int M, int C) {
    int lane = threadIdx.x & 31;
    int rg   = threadIdx.x >> 5;    // 0..7
    int col  = blockIdx.x * 32 + lane;
    float s = 0.0f, s2 = 0.0f;
    if (col < C) {
        for (int r = rg; r < M; r += 8) {
            float v = X[(size_t)r * C + col];
            s += v; s2 += v * v;
        }
    }
    __shared__ float sh[8][32], sh2[8][32];
    sh[rg][lane] = s; sh2[rg][lane] = s2;
    __syncthreads();
    if (rg == 0 && col < C) {
        #pragma unroll
        for (int i = 1; i < 8; i++) { s += sh[i][lane]; s2 += sh2[i][lane]; }
        float mu  = s / (float)M;
        float var = s2 / (float)M - mu * mu;
        float sc  = gamma[col] * rsqrtf(var + EPS);
        scale[col] = sc;
        shift[col] = beta[col] - mu * sc;
    }
}

// ---------------- BN apply + leaky relu ----------------
// grid: (C/256, N)
__global__ void bn_apply(const float* __restrict__ X, float* __restrict__ Y,
                         const float* __restrict__ scale, const float* __restrict__ shift,
                         int C) {
    int row = blockIdx.y;
    int c = blockIdx.x * blockDim.x + threadIdx.x;
    if (c >= C) return;
    float v = X[(size_t)row * C + c] * scale[c] + shift[c];
    Y[(size_t)row * C + c] = (v > 0.0f) ? v : SLOPE * v;
}

// ---------------- pooling ----------------
__global__ void cnt_kernel(const int* __restrict__ gid, float* __restrict__ cnt) {
    int i = blockIdx.x * blockDim.x + threadIdx.x;
    if (i < Nn) atomicAdd(&cnt[gid[i]], 1.0f);
}

// grid: (C/256, N)
__global__ void pool_kernel(const float* __restrict__ x, const int* __restrict__ gid,
                            float* __restrict__ hg, int C) {
    int row = blockIdx.y;
    int c = blockIdx.x * blockDim.x + threadIdx.x;
    if (c >= C) return;
    atomicAdd(&hg[(size_t)gid[row] * C + c], x[(size_t)row * C + c]);
}

// grid: (C/256, G)
__global__ void hg_div(float* __restrict__ hg, const float* __restrict__ cnt, int C) {
    int g = blockIdx.y;
    int c = blockIdx.x * blockDim.x + threadIdx.x;
    if (c >= C) return;
    hg[(size_t)g * C + c] *= 1.0f / fmaxf(cnt[g], 1.0f);
}

// ---------------- small MLP head GEMM (M = 64 rows) ----------------
// grid: (ceil(Nc/128), G), 128 threads, dyn smem = K*4
__global__ void head_gemm(const float* __restrict__ X, const float* __restrict__ W,
                          const float* __restrict__ b, float* __restrict__ Y,
                          int K, int Nc, int do_lrelu) {
    extern __shared__ float xs[];
    int r = blockIdx.y;
    for (int i = threadIdx.x; i < K; i += blockDim.x) xs[i] = X[(size_t)r * K + i];
    __syncthreads();
    int c = blockIdx.x * blockDim.x + threadIdx.x;
    if (c >= Nc) return;
    float acc = 0.0f;
    int k = 0;
    for (; k + 4 <= K; k += 4) {
        acc += xs[k    ] * W[(size_t)(k    ) * Nc + c];
        acc += xs[k + 1] * W[(size_t)(k + 1) * Nc + c];
        acc += xs[k + 2] * W[(size_t)(k + 2) * Nc + c];
        acc += xs[k + 3] * W[(size_t)(k + 3) * Nc + c];
    }
    for (; k < K; k++) acc += xs[k] * W[(size_t)k * Nc + c];
    acc += b[c];
    if (do_lrelu) acc = (acc > 0.0f) ? acc : SLOPE * acc;
    Y[(size_t)r * Nc + c] = acc;
}

// ---------------- launch ----------------
extern "C" void kernel_launch(void* const* d_in, const int* in_sizes, int n_in,
                              void* d_out, int out_size) {
    (void)in_sizes; (void)n_in; (void)out_size;
    const float* h     = (const float*)d_in[0];
    const int*   src   = (const int*)  d_in[1];
    const int*   dst   = (const int*)  d_in[2];
    const int*   gid   = (const int*)  d_in[3];
    const float* Ws1   = (const float*)d_in[4];
    const float* Wn1   = (const float*)d_in[5];
    const float* b1    = (const float*)d_in[6];
    const float* Ws2   = (const float*)d_in[7];
    const float* Wn2   = (const float*)d_in[8];
    const float* b2    = (const float*)d_in[9];
    const float* Ws3   = (const float*)d_in[10];
    const float* Wn3   = (const float*)d_in[11];
    const float* b3    = (const float*)d_in[12];
    const float* g1    = (const float*)d_in[13];
    const float* be1   = (const float*)d_in[14];
    const float* g2    = (const float*)d_in[15];
    const float* be2   = (const float*)d_in[16];
    const float* g3    = (const float*)d_in[17];
    const float* be3   = (const float*)d_in[18];
    const float* fc1_w = (const float*)d_in[19];
    const float* fc1_b = (const float*)d_in[20];
    const float* fc2_w = (const float*)d_in[21];
    const float* fc2_b = (const float*)d_in[22];
    const float* fc3_w = (const float*)d_in[23];
    const float* fc3_b = (const float*)d_in[24];
    float* out = (float*)d_out;

    float *nm, *x, *y, *deg, *scale, *shift, *hg, *cnt, *t1, *t2;
    cudaGetSymbolAddress((void**)&nm,    g_nm);
    cudaGetSymbolAddress((void**)&x,     g_x);
    cudaGetSymbolAddress((void**)&y,     g_y);
    cudaGetSymbolAddress((void**)&deg,   g_deg);
    cudaGetSymbolAddress((void**)&scale, g_scale);
    cudaGetSymbolAddress((void**)&shift, g_shift);
    cudaGetSymbolAddress((void**)&hg,    g_hg);
    cudaGetSymbolAddress((void**)&cnt,   g_cnt);
    cudaGetSymbolAddress((void**)&t1,    g_t1);
    cudaGetSymbolAddress((void**)&t2,    g_t2);

    cudaStream_t s = 0;

    // degrees (shared by all layers)
    cudaMemsetAsync(deg, 0, Nn * sizeof(float), s);
    deg_kernel<<<Ee / 256, 256, 0, s>>>(dst, deg);

    dim3 gemm_grid(HID / BN, Nn / BM);

    // ---- Layer 1 (K = 63) ----
    cudaMemsetAsync(nm, 0, (size_t)Nn * INF * sizeof(float), s);
    scatter_add<<<dim3(Ee, 1), 64, 0, s>>>(h, src, dst, nm, INF);
    row_div<<<dim3(1, Nn), 64, 0, s>>>(nm, deg, INF);
    sgemm_dual<<<gemm_grid, 256, 0, s>>>(h, Ws1, nm, Wn1, b1, y, Nn, HID, INF, 0);
    bn_stats<<<HID / 32, 256, 0, s>>>(y, g1, be1, scale, shift, Nn, HID);
    bn_apply<<<dim3(HID / 256, Nn), 256, 0, s>>>(y, x, scale, shift, HID);

    // ---- Layer 2 (K = 2048) ----
    cudaMemsetAsync(nm, 0, (size_t)Nn * HID * sizeof(float), s);
    scatter_add<<<dim3(Ee, HID / 256), 256, 0, s>>>(x, src, dst, nm, HID);
    row_div<<<dim3(HID / 256, Nn), 256, 0, s>>>(nm, deg, HID);
    sgemm_dual<<<gemm_grid, 256, 0, s>>>(x, Ws2, nm, Wn2, b2, y, Nn, HID, HID, 0);
    bn_stats<<<HID / 32, 256, 0, s>>>(y, g2, be2, scale, shift, Nn, HID);
    bn_apply<<<dim3(HID / 256, Nn), 256, 0, s>>>(y, x, scale, shift, HID);

    // ---- Layer 3 (K = 2048) ----
    cudaMemsetAsync(nm, 0, (size_t)Nn * HID * sizeof(float), s);
    scatter_add<<<dim3(Ee, HID / 256), 256, 0, s>>>(x, src, dst, nm, HID);
    row_div<<<dim3(HID / 256, Nn), 256, 0, s>>>(nm, deg, HID);
    sgemm_dual<<<gemm_grid, 256, 0, s>>>(x, Ws3, nm, Wn3, b3, y, Nn, HID, HID, 0);
    bn_stats<<<HID / 32, 256, 0, s>>>(y, g3, be3, scale, shift, Nn, HID);
    bn_apply<<<dim3(HID / 256, Nn), 256, 0, s>>>(y, x, scale, shift, HID);

    // ---- Average pooling over graphs ----
    cudaMemsetAsync(hg, 0, Gg * HID * sizeof(float), s);
    cudaMemsetAsync(cnt, 0, Gg * sizeof(float), s);
    cnt_kernel<<<Nn / 256, 256, 0, s>>>(gid, cnt);
    pool_kernel<<<dim3(HID / 256, Nn), 256, 0, s>>>(x, gid, hg, HID);
    hg_div<<<dim3(HID / 256, Gg), 256, 0, s>>>(hg, cnt, HID);

    // ---- MLP head ----
    head_gemm<<<dim3((HID + 127) / 128, Gg), 128, HID * sizeof(float), s>>>(
        hg, fc1_w, fc1_b, t1, HID, HID, 1);
    head_gemm<<<dim3((MIDD + 127) / 128, Gg), 128, HID * sizeof(float), s>>>(
        t1, fc2_w, fc2_b, t2, HID, MIDD, 1);
    head_gemm<<<dim3(1, Gg), 128, MIDD * sizeof(float), s>>>(
        t2, fc3_w, fc3_b, out, MIDD, NCLS, 0);
}

// round 3
// speedup vs baseline: 2.6510x; 2.6510x over previous
#include <cuda_runtime.h>
#include <cstdint>
#include <math.h>

// Problem constants
#define Nn   16384
#define Ee   65536
#define Gg   64
#define INF  63
#define HID  2048
#define MIDD 1024
#define NCLS 18
#define SLOPE 0.01f
#define EPS   1e-5f

// ---------------- scratch (device globals; no allocation allowed) ----------------
__device__ float g_nm[(size_t)Nn * HID];   // neighbor mean buffer
__device__ float g_x [(size_t)Nn * HID];   // current activations (tf32-rounded when feeding TC GEMM)
__device__ float g_y [(size_t)Nn * HID];   // GEMM output
__device__ float g_deg[Nn];
__device__ float g_scale[HID];
__device__ float g_shift[HID];
__device__ float g_hg[Gg * HID];
__device__ float g_cnt[Gg];
__device__ float g_t1[Gg * HID];
__device__ float g_t2[Gg * MIDD];
// transposed + tf32-rounded weights [N=HID rows, K=HID cols] (K-major)
__device__ float g_wt2s[(size_t)HID * HID];
__device__ float g_wt2n[(size_t)HID * HID];
__device__ float g_wt3s[(size_t)HID * HID];
__device__ float g_wt3n[(size_t)HID * HID];

// ==================== helpers ====================
__device__ __forceinline__ uint32_t smem_u32(const void* p) {
    uint32_t a;
    asm("{ .reg .u64 t; cvta.to.shared.u64 t, %1; cvt.u32.u64 %0, t; }" : "=r"(a) : "l"(p));
    return a;
}
__device__ __forceinline__ uint32_t f2tf32(float v) {
    uint32_t r; asm("cvt.rna.tf32.f32 %0, %1;" : "=r"(r) : "f"(v)); return r;
}
__device__ __forceinline__ void cp_async16(uint32_t dst, const void* src) {
    asm volatile("cp.async.cg.shared.global [%0], [%1], 16;" :: "r"(dst), "l"(src) : "memory");
}
__device__ __forceinline__ void cp_commit() {
    asm volatile("cp.async.commit_group;" ::: "memory");
}

__device__ __forceinline__ void mma_tf32(float* d, const uint32_t* a, const uint32_t* b) {
    asm volatile(
        "mma.sync.aligned.m16n8k8.row.col.f32.tf32.tf32.f32 "
        "{%0,%1,%2,%3}, {%4,%5,%6,%7}, {%8,%9}, {%0,%1,%2,%3};"
        : "+f"(d[0]), "+f"(d[1]), "+f"(d[2]), "+f"(d[3])
        : "r"(a[0]), "r"(a[1]), "r"(a[2]), "r"(a[3]), "r"(b[0]), "r"(b[1]));
}

// ==================== tf32 mma.sync dual-source GEMM ====================
// C[M=16384, N=2048] = A1@B1^T + A2@B2^T + bias.  K = 2048 per source.
// A row-major [M,K]; B pre-transposed row-major [N,K]. All values tf32-prerounded.
// CTA tile 128x128, 8 warps (2m x 4n), warp tile 64x32, K-chunk 32, double-buffered.
#define PADF 36                                   // floats per smem row (bank-conflict-free, 16B-aligned)
#define OP_FLOATS (128 * PADF)                    // one operand tile
#define STAGE_FLOATS (2 * OP_FLOATS)              // A + B
#define TCG_SMEM_BYTES (2 * STAGE_FLOATS * 4)     // 2 stages = 73728 B

__global__ void __launch_bounds__(256, 2)
tc_gemm_dual(const float* __restrict__ A1, const float* __restrict__ B1,
             const float* __restrict__ A2, const float* __restrict__ B2,
             const float* __restrict__ bias, float* __restrict__ C) {
    extern __shared__ __align__(16) float smem[];
    uint32_t sb = smem_u32(smem);
    const int tid  = threadIdx.x;
    const int wid  = tid >> 5;
    const int lane = tid & 31;
    const int rowBlk = blockIdx.y * 128;
    const int colBlk = blockIdx.x * 128;
    const int wm = (wid & 1) * 64;   // warp m offset
    const int wn = (wid >> 1) * 32;  // warp n offset

    const int lr = lane >> 2;  // 0..7
    const int lc = lane & 3;   // 0..3

    float acc[4][4][4];
    #pragma unroll
    for (int i = 0; i < 4; i++)
        #pragma unroll
        for (int j = 0; j < 4; j++)
            #pragma unroll
            for (int k = 0; k < 4; k++) acc[i][j][k] = 0.0f;

    const int NC  = HID / 32;   // 64 chunks per source
    const int TOT = 2 * NC;     // 128

    // issue load of chunk 0 into stage 0
    {
        const float* A = A1; const float* B = B1;
        #pragma unroll
        for (int i = 0; i < 4; i++) {
            int t = tid + i * 256;
            int r = t >> 3, sg = t & 7;
            uint32_t off = (uint32_t)r * (PADF * 4) + (uint32_t)sg * 16;
            cp_async16(sb + off, A + (size_t)(rowBlk + r) * HID + sg * 4);
            cp_async16(sb + OP_FLOATS * 4 + off, B + (size_t)(colBlk + r) * HID + sg * 4);
        }
        cp_commit();
    }

    for (int c = 0; c < TOT; c++) {
        int s = c & 1;
        // prefetch chunk c+1 into stage s^1
        if (c + 1 < TOT) {
            int n2 = c + 1;
            const float* A = (n2 < NC) ? A1 : A2;
            const float* B = (n2 < NC) ? B1 : B2;
            int k0 = (n2 & (NC - 1)) * 32;
            uint32_t base = sb + (uint32_t)(s ^ 1) * (STAGE_FLOATS * 4);
            #pragma unroll
            for (int i = 0; i < 4; i++) {
                int t = tid + i * 256;
                int r = t >> 3, sg = t & 7;
                uint32_t off = (uint32_t)r * (PADF * 4) + (uint32_t)sg * 16;
                cp_async16(base + off, A + (size_t)(rowBlk + r) * HID + k0 + sg * 4);
                cp_async16(base + OP_FLOATS * 4 + off, B + (size_t)(colBlk + r) * HID + k0 + sg * 4);
            }
            cp_commit();
            asm volatile("cp.async.wait_group 1;" ::: "memory");
        } else {
            asm volatile("cp.async.wait_group 0;" ::: "memory");
        }
        __syncthreads();

        const uint32_t* As = (const uint32_t*)(smem + (size_t)s * STAGE_FLOATS);
        const uint32_t* Bs = As + OP_FLOATS;

        #pragma unroll
        for (int kp = 0; kp < 32; kp += 8) {
            uint32_t af[4][4], bf[4][2];
            #pragma unroll
            for (int mt = 0; mt < 4; mt++) {
                int r0 = wm + mt * 16 + lr;
                int cc = kp + lc;
                af[mt][0] = As[r0 * PADF + cc];
                af[mt][1] = As[(r0 + 8) * PADF + cc];
                af[mt][2] = As[r0 * PADF + cc + 4];
                af[mt][3] = As[(r0 + 8) * PADF + cc + 4];
            }
            #pragma unroll
            for (int nt = 0; nt < 4; nt++) {
                int n0 = wn + nt * 8 + lr;
                int kk = kp + lc;
                bf[nt][0] = Bs[n0 * PADF + kk];
                bf[nt][1] = Bs[n0 * PADF + kk + 4];
            }
            #pragma unroll
            for (int mt = 0; mt < 4; mt++)
                #pragma unroll
                for (int nt = 0; nt < 4; nt++)
                    mma_tf32(acc[mt][nt], af[mt], bf[nt]);
        }
        __syncthreads();
    }

    // epilogue: accumulator -> global (+bias)
    #pragma unroll
    for (int mt = 0; mt < 4; mt++) {
        #pragma unroll
        for (int nt = 0; nt < 4; nt++) {
            int gr = rowBlk + wm + mt * 16 + lr;
            int gc = colBlk + wn + nt * 8 + 2 * lc;
            float bv0 = bias[gc], bv1 = bias[gc + 1];
            float2 v0 = make_float2(acc[mt][nt][0] + bv0, acc[mt][nt][1] + bv1);
            float2 v1 = make_float2(acc[mt][nt][2] + bv0, acc[mt][nt][3] + bv1);
            *(float2*)&C[(size_t)gr * HID + gc]       = v0;
            *(float2*)&C[(size_t)(gr + 8) * HID + gc] = v1;
        }
    }
}

// ==================== weight transpose + tf32 round ====================
// W [K,N] row-major -> Wt [N,K] row-major, values rounded to tf32 (RNA).
__global__ void transpose_cvt(const float* __restrict__ W, float* __restrict__ Wt) {
    __shared__ float tile[32][33];
    int n0 = blockIdx.x * 32, k0 = blockIdx.y * 32;
    int tx = threadIdx.x, ty = threadIdx.y;
    #pragma unroll
    for (int j = 0; j < 4; j++)
        tile[ty + j * 8][tx] = W[(size_t)(k0 + ty + j * 8) * HID + (n0 + tx)];
    __syncthreads();
    #pragma unroll
    for (int j = 0; j < 4; j++) {
        uint32_t u = f2tf32(tile[tx][ty + j * 8]);
        Wt[(size_t)(n0 + ty + j * 8) * HID + (k0 + tx)] = __uint_as_float(u);
    }
}

// ==================== graph / elementwise kernels ====================
__global__ void deg_kernel(const int* __restrict__ dst, float* __restrict__ deg) {
    int i = blockIdx.x * blockDim.x + threadIdx.x;
    if (i < Ee) atomicAdd(&deg[dst[i]], 1.0f);
}

__global__ void scatter_add(const float* __restrict__ x, const int* __restrict__ src,
                            const int* __restrict__ dst, float* __restrict__ out, int F) {
    int e = blockIdx.x;
    int f = blockIdx.y * blockDim.x + threadIdx.x;
    if (f >= F) return;
    int s = src[e], d = dst[e];
    atomicAdd(&out[(size_t)d * F + f], x[(size_t)s * F + f]);
}

// divide rows by max(deg,1); optionally tf32-round the result
__global__ void row_div(float* __restrict__ nm, const float* __restrict__ deg, int F, int do_cvt) {
    int row = blockIdx.y;
    int f = blockIdx.x * blockDim.x + threadIdx.x;
    if (f >= F) return;
    float d = deg[row];
    float v = nm[(size_t)row * F + f] * (1.0f / fmaxf(d, 1.0f));
    if (do_cvt) v = __uint_as_float(f2tf32(v));
    nm[(size_t)row * F + f] = v;
}

// ---------------- fp32 SGEMM (layer 1, K = 63) ----------------
#define BM 128
#define BN 128
#define BK 16
#define TM 8
#define TN 8

__global__ __launch_bounds__(256, 2)
void sgemm_dual(const float* __restrict__ A1, const float* __restrict__ W1,
                const float* __restrict__ A2, const float* __restrict__ W2,
                const float* __restrict__ bias, float* __restrict__ C,
                int M, int Nc, int K) {
    __shared__ float As[BK][BM + 4];
    __shared__ float Bs[BK][BN];
    int tid = threadIdx.x;
    int block_row = blockIdx.y * BM;
    int block_col = blockIdx.x * BN;
    int tr = tid / (BN / TN);
    int tc = tid % (BN / TN);

    float acc[TM][TN];
    #pragma unroll
    for (int i = 0; i < TM; i++)
        #pragma unroll
        for (int j = 0; j < TN; j++) acc[i][j] = 0.0f;

    for (int s = 0; s < 2; s++) {
        const float* A = s ? A2 : A1;
        const float* W = s ? W2 : W1;
        for (int k0 = 0; k0 < K; k0 += BK) {
            #pragma unroll
            for (int i = tid; i < BM * BK; i += 256) {
                int m = i / BK, k = i % BK;
                int gr = block_row + m, gk = k0 + k;
                As[k][m] = (gr < M && gk < K) ? A[(size_t)gr * K + gk] : 0.0f;
            }
            #pragma unroll
            for (int i = tid; i < BK * BN; i += 256) {
                int k = i / BN, n = i % BN;
                int gk = k0 + k, gc = block_col + n;
                Bs[k][n] = (gk < K && gc < Nc) ? W[(size_t)gk * Nc + gc] : 0.0f;
            }
            __syncthreads();
            #pragma unroll
            for (int k = 0; k < BK; k++) {
                float ra[TM], rb[TN];
                #pragma unroll
                for (int i = 0; i < TM; i++) ra[i] = As[k][tr * TM + i];
                #pragma unroll
                for (int j = 0; j < TN; j++) rb[j] = Bs[k][tc * TN + j];
                #pragma unroll
                for (int i = 0; i < TM; i++)
                    #pragma unroll
                    for (int j = 0; j < TN; j++)
                        acc[i][j] += ra[i] * rb[j];
            }
            __syncthreads();
        }
    }
    #pragma unroll
    for (int i = 0; i < TM; i++) {
        int gr = block_row + tr * TM + i;
        if (gr >= M) continue;
        #pragma unroll
        for (int j = 0; j < TN; j++) {
            int gc = block_col + tc * TN + j;
            if (gc >= Nc) continue;
            C[(size_t)gr * Nc + gc] = acc[i][j] + (bias ? bias[gc] : 0.0f);
        }
    }
}

// ---------------- BN stats ----------------
__global__ void bn_stats(const float* __restrict__ X,
                         const float* __restrict__ gamma, const float* __restrict__ beta,
                         float* __restrict__ scale, float* __restrict__ shift,
                         int M, int C) {
    int lane = threadIdx.x & 31;
    int rg   = threadIdx.x >> 5;
    int col  = blockIdx.x * 32 + lane;
    float s = 0.0f, s2 = 0.0f;
    if (col < C) {
        for (int r = rg; r < M; r += 8) {
            float v = X[(size_t)r * C + col];
            s += v; s2 += v * v;
        }
    }
    __shared__ float sh[8][32], sh2[8][32];
    sh[rg][lane] = s; sh2[rg][lane] = s2;
    __syncthreads();
    if (rg == 0 && col < C) {
        #pragma unroll
        for (int i = 1; i < 8; i++) { s += sh[i][lane]; s2 += sh2[i][lane]; }
        float mu  = s / (float)M;
        float var = s2 / (float)M - mu * mu;
        float sc  = gamma[col] * rsqrtf(var + EPS);
        scale[col] = sc;
        shift[col] = beta[col] - mu * sc;
    }
}

// BN apply + leaky relu, optionally tf32-round result
__global__ void bn_apply(const float* __restrict__ X, float* __restrict__ Y,
                         const float* __restrict__ scale, const float* __restrict__ shift,
                         int C, int do_cvt) {
    int row = blockIdx.y;
    int c = blockIdx.x * blockDim.x + threadIdx.x;
    if (c >= C) return;
    float v = X[(size_t)row * C + c] * scale[c] + shift[c];
    v = (v > 0.0f) ? v : SLOPE * v;
    if (do_cvt) v = __uint_as_float(f2tf32(v));
    Y[(size_t)row * C + c] = v;
}

// ---------------- pooling ----------------
__global__ void cnt_kernel(const int* __restrict__ gid, float* __restrict__ cnt) {
    int i = blockIdx.x * blockDim.x + threadIdx.x;
    if (i < Nn) atomicAdd(&cnt[gid[i]], 1.0f);
}

__global__ void pool_kernel(const float* __restrict__ x, const int* __restrict__ gid,
                            float* __restrict__ hg, int C) {
    int row = blockIdx.y;
    int c = blockIdx.x * blockDim.x + threadIdx.x;
    if (c >= C) return;
    atomicAdd(&hg[(size_t)gid[row] * C + c], x[(size_t)row * C + c]);
}

__global__ void hg_div(float* __restrict__ hg, const float* __restrict__ cnt, int C) {
    int g = blockIdx.y;
    int c = blockIdx.x * blockDim.x + threadIdx.x;
    if (c >= C) return;
    hg[(size_t)g * C + c] *= 1.0f / fmaxf(cnt[g], 1.0f);
}

// ---------------- small MLP head GEMM ----------------
__global__ void head_gemm(const float* __restrict__ X, const float* __restrict__ W,
                          const float* __restrict__ b, float* __restrict__ Y,
                          int K, int Nc, int do_lrelu) {
    extern __shared__ float xs[];
    int r = blockIdx.y;
    for (int i = threadIdx.x; i < K; i += blockDim.x) xs[i] = X[(size_t)r * K + i];
    __syncthreads();
    int c = blockIdx.x * blockDim.x + threadIdx.x;
    if (c >= Nc) return;
    float acc = 0.0f;
    int k = 0;
    for (; k + 4 <= K; k += 4) {
        acc += xs[k    ] * W[(size_t)(k    ) * Nc + c];
        acc += xs[k + 1] * W[(size_t)(k + 1) * Nc + c];
        acc += xs[k + 2] * W[(size_t)(k + 2) * Nc + c];
        acc += xs[k + 3] * W[(size_t)(k + 3) * Nc + c];
    }
    for (; k < K; k++) acc += xs[k] * W[(size_t)k * Nc + c];
    acc += b[c];
    if (do_lrelu) acc = (acc > 0.0f) ? acc : SLOPE * acc;
    Y[(size_t)r * Nc + c] = acc;
}

// ==================== launch ====================
extern "C" void kernel_launch(void* const* d_in, const int* in_sizes, int n_in,
                              void* d_out, int out_size) {
    (void)in_sizes; (void)n_in; (void)out_size;
    const float* h     = (const float*)d_in[0];
    const int*   src   = (const int*)  d_in[1];
    const int*   dst   = (const int*)  d_in[2];
    const int*   gid   = (const int*)  d_in[3];
    const float* Ws1   = (const float*)d_in[4];
    const float* Wn1   = (const float*)d_in[5];
    const float* b1    = (const float*)d_in[6];
    const float* Ws2   = (const float*)d_in[7];
    const float* Wn2   = (const float*)d_in[8];
    const float* b2    = (const float*)d_in[9];
    const float* Ws3   = (const float*)d_in[10];
    const float* Wn3   = (const float*)d_in[11];
    const float* b3    = (const float*)d_in[12];
    const float* g1    = (const float*)d_in[13];
    const float* be1   = (const float*)d_in[14];
    const float* g2    = (const float*)d_in[15];
    const float* be2   = (const float*)d_in[16];
    const float* g3    = (const float*)d_in[17];
    const float* be3   = (const float*)d_in[18];
    const float* fc1_w = (const float*)d_in[19];
    const float* fc1_b = (const float*)d_in[20];
    const float* fc2_w = (const float*)d_in[21];
    const float* fc2_b = (const float*)d_in[22];
    const float* fc3_w = (const float*)d_in[23];
    const float* fc3_b = (const float*)d_in[24];
    float* out = (float*)d_out;

    float *nm, *x, *y, *deg, *scale, *shift, *hg, *cnt, *t1, *t2;
    float *wt2s, *wt2n, *wt3s, *wt3n;
    cudaGetSymbolAddress((void**)&nm,    g_nm);
    cudaGetSymbolAddress((void**)&x,     g_x);
    cudaGetSymbolAddress((void**)&y,     g_y);
    cudaGetSymbolAddress((void**)&deg,   g_deg);
    cudaGetSymbolAddress((void**)&scale, g_scale);
    cudaGetSymbolAddress((void**)&shift, g_shift);
    cudaGetSymbolAddress((void**)&hg,    g_hg);
    cudaGetSymbolAddress((void**)&cnt,   g_cnt);
    cudaGetSymbolAddress((void**)&t1,    g_t1);
    cudaGetSymbolAddress((void**)&t2,    g_t2);
    cudaGetSymbolAddress((void**)&wt2s,  g_wt2s);
    cudaGetSymbolAddress((void**)&wt2n,  g_wt2n);
    cudaGetSymbolAddress((void**)&wt3s,  g_wt3s);
    cudaGetSymbolAddress((void**)&wt3n,  g_wt3n);

    cudaFuncSetAttribute(tc_gemm_dual, cudaFuncAttributeMaxDynamicSharedMemorySize, TCG_SMEM_BYTES);

    cudaStream_t s = 0;

    // weight transposes (+ tf32 rounding)
    dim3 tgrid(HID / 32, HID / 32), tblk(32, 8);
    transpose_cvt<<<tgrid, tblk, 0, s>>>(Ws2, wt2s);
    transpose_cvt<<<tgrid, tblk, 0, s>>>(Wn2, wt2n);
    transpose_cvt<<<tgrid, tblk, 0, s>>>(Ws3, wt3s);
    transpose_cvt<<<tgrid, tblk, 0, s>>>(Wn3, wt3n);

    // degrees
    cudaMemsetAsync(deg, 0, Nn * sizeof(float), s);
    deg_kernel<<<Ee / 256, 256, 0, s>>>(dst, deg);

    dim3 tc_grid(HID / 128, Nn / 128);

    // ---- Layer 1 (K = 63, fp32 SGEMM) ----
    cudaMemsetAsync(nm, 0, (size_t)Nn * INF * sizeof(float), s);
    scatter_add<<<dim3(Ee, 1), 64, 0, s>>>(h, src, dst, nm, INF);
    row_div<<<dim3(1, Nn), 64, 0, s>>>(nm, deg, INF, 0);
    sgemm_dual<<<dim3(HID / BN, Nn / BM), 256, 0, s>>>(h, Ws1, nm, Wn1, b1, y, Nn, HID, INF);
    bn_stats<<<HID / 32, 256, 0, s>>>(y, g1, be1, scale, shift, Nn, HID);
    bn_apply<<<dim3(HID / 256, Nn), 256, 0, s>>>(y, x, scale, shift, HID, 1);

    // ---- Layer 2 (tf32 mma.sync) ----
    cudaMemsetAsync(nm, 0, (size_t)Nn * HID * sizeof(float), s);
    scatter_add<<<dim3(Ee, HID / 256), 256, 0, s>>>(x, src, dst, nm, HID);
    row_div<<<dim3(HID / 256, Nn), 256, 0, s>>>(nm, deg, HID, 1);
    tc_gemm_dual<<<tc_grid, 256, TCG_SMEM_BYTES, s>>>(x, wt2s, nm, wt2n, b2, y);
    bn_stats<<<HID / 32, 256, 0, s>>>(y, g2, be2, scale, shift, Nn, HID);
    bn_apply<<<dim3(HID / 256, Nn), 256, 0, s>>>(y, x, scale, shift, HID, 1);

    // ---- Layer 3 (tf32 mma.sync) ----
    cudaMemsetAsync(nm, 0, (size_t)Nn * HID * sizeof(float), s);
    scatter_add<<<dim3(Ee, HID / 256), 256, 0, s>>>(x, src, dst, nm, HID);
    row_div<<<dim3(HID / 256, Nn), 256, 0, s>>>(nm, deg, HID, 1);
    tc_gemm_dual<<<tc_grid, 256, TCG_SMEM_BYTES, s>>>(x, wt3s, nm, wt3n, b3, y);
    bn_stats<<<HID / 32, 256, 0, s>>>(y, g3, be3, scale, shift, Nn, HID);
    bn_apply<<<dim3(HID / 256, Nn), 256, 0, s>>>(y, x, scale, shift, HID, 0);

    // ---- Average pooling over graphs ----
    cudaMemsetAsync(hg, 0, Gg * HID * sizeof(float), s);
    cudaMemsetAsync(cnt, 0, Gg * sizeof(float), s);
    cnt_kernel<<<Nn / 256, 256, 0, s>>>(gid, cnt);
    pool_kernel<<<dim3(HID / 256, Nn), 256, 0, s>>>(x, gid, hg, HID);
    hg_div<<<dim3(HID / 256, Gg), 256, 0, s>>>(hg, cnt, HID);

    // ---- MLP head ----
    head_gemm<<<dim3((HID + 127) / 128, Gg), 128, HID * sizeof(float), s>>>(
        hg, fc1_w, fc1_b, t1, HID, HID, 1);
    head_gemm<<<dim3((MIDD + 127) / 128, Gg), 128, HID * sizeof(float), s>>>(
        t1, fc2_w, fc2_b, t2, HID, MIDD, 1);
    head_gemm<<<dim3(1, Gg), 128, MIDD * sizeof(float), s>>>(
        t2, fc3_w, fc3_b, out, MIDD, NCLS, 0);
}